// round 1
// baseline (speedup 1.0000x reference)
#include <cuda_runtime.h>

#define NB   8
#define CIN  256
#define HW   4096
#define CATT 128
#define COUT 256

// Scratch (device globals; no allocation allowed)
__device__ float g_feat[(size_t)NB * COUT * HW];              // 33.5 MB
__device__ float g_att [(size_t)NB * CATT * HW];              // 16.8 MB
__device__ float g_energy[(size_t)NB * HW * HW];              // 537 MB

// ---------------------------------------------------------------------------
// Kernel 1: 1x1 conv + BN(eval) + ReLU.  Per batch: Y[o,p] = sum_c W[o,c]*X[c,p]
// W: [OC, CIN] row-major, X: [CIN, HW] row-major. 64x64 tile, 16x16 thr, 4x4.
// dest: 0 -> g_feat (OC=COUT), 1 -> g_att (OC=CATT)
// ---------------------------------------------------------------------------
__global__ void conv_bn_relu_kernel(const float* __restrict__ x,
                                    const float* __restrict__ w,
                                    const float* __restrict__ gamma,
                                    const float* __restrict__ beta,
                                    const float* __restrict__ mean,
                                    const float* __restrict__ var,
                                    int OC, int dest) {
    __shared__ float As[16][64];   // As[k][m] = W[o0+m, k0+k]
    __shared__ float Bs[16][64];   // Bs[k][p] = X[k0+k, p0+p]

    const int n  = blockIdx.z;
    const int p0 = blockIdx.x * 64;
    const int o0 = blockIdx.y * 64;
    const int tx = threadIdx.x, ty = threadIdx.y;
    const int tid = ty * 16 + tx;
    const float* X = x + (size_t)n * CIN * HW;
    float* out = dest ? g_att : g_feat;

    float acc[4][4] = {};

    for (int k0 = 0; k0 < CIN; k0 += 16) {
        #pragma unroll
        for (int i = tid; i < 64 * 16; i += 256) {
            int m = i >> 4, k = i & 15;
            As[k][m] = w[(size_t)(o0 + m) * CIN + k0 + k];
        }
        #pragma unroll
        for (int i = tid; i < 16 * 64; i += 256) {
            int k = i >> 6, p = i & 63;
            Bs[k][p] = X[(size_t)(k0 + k) * HW + p0 + p];
        }
        __syncthreads();
        #pragma unroll
        for (int k = 0; k < 16; k++) {
            float a[4], b[4];
            #pragma unroll
            for (int i = 0; i < 4; i++) a[i] = As[k][ty * 4 + i];
            #pragma unroll
            for (int j = 0; j < 4; j++) b[j] = Bs[k][tx * 4 + j];
            #pragma unroll
            for (int i = 0; i < 4; i++)
                #pragma unroll
                for (int j = 0; j < 4; j++)
                    acc[i][j] = fmaf(a[i], b[j], acc[i][j]);
        }
        __syncthreads();
    }

    #pragma unroll
    for (int i = 0; i < 4; i++) {
        int o = o0 + ty * 4 + i;
        float inv  = gamma[o] * rsqrtf(var[o] + 1e-5f);
        float bias = beta[o] - mean[o] * inv;
        #pragma unroll
        for (int j = 0; j < 4; j++) {
            int p = p0 + tx * 4 + j;
            float v = acc[i][j] * inv + bias;
            out[((size_t)n * OC + o) * HW + p] = fmaxf(v, 0.0f);
        }
    }
}

// ---------------------------------------------------------------------------
// Kernel 2: energy[n,i,j] = inv_s * sum_c Q[c,i]*Q[c,j] + (mask[n,j]-1)*1e8
// Q = g_att[n] : [CATT, HW] row-major (position contiguous)
// ---------------------------------------------------------------------------
__global__ void energy_kernel(const float* __restrict__ mask) {
    __shared__ float As[16][64];   // As[k][m] = Q[k0+k, i0+m]
    __shared__ float Bs[16][64];   // Bs[k][p] = Q[k0+k, j0+p]

    const int n  = blockIdx.z;
    const int j0 = blockIdx.x * 64;
    const int i0 = blockIdx.y * 64;
    const int tx = threadIdx.x, ty = threadIdx.y;
    const int tid = ty * 16 + tx;
    const float* Q = g_att + (size_t)n * CATT * HW;

    float acc[4][4] = {};

    for (int k0 = 0; k0 < CATT; k0 += 16) {
        #pragma unroll
        for (int i = tid; i < 16 * 64; i += 256) {
            int k = i >> 6, m = i & 63;
            As[k][m] = Q[(size_t)(k0 + k) * HW + i0 + m];
        }
        #pragma unroll
        for (int i = tid; i < 16 * 64; i += 256) {
            int k = i >> 6, p = i & 63;
            Bs[k][p] = Q[(size_t)(k0 + k) * HW + j0 + p];
        }
        __syncthreads();
        #pragma unroll
        for (int k = 0; k < 16; k++) {
            float a[4], b[4];
            #pragma unroll
            for (int i = 0; i < 4; i++) a[i] = As[k][ty * 4 + i];
            #pragma unroll
            for (int j = 0; j < 4; j++) b[j] = Bs[k][tx * 4 + j];
            #pragma unroll
            for (int i = 0; i < 4; i++)
                #pragma unroll
                for (int j = 0; j < 4; j++)
                    acc[i][j] = fmaf(a[i], b[j], acc[i][j]);
        }
        __syncthreads();
    }

    const float inv_s = 0.08838834764831845f;   // 1/(1e-8 + sqrt(128))
    #pragma unroll
    for (int i = 0; i < 4; i++) {
        int ii = i0 + ty * 4 + i;
        #pragma unroll
        for (int j = 0; j < 4; j++) {
            int jj = j0 + tx * 4 + j;
            float mterm = (mask[(size_t)n * HW + jj] - 1.0f) * 1e8f;
            g_energy[((size_t)n * HW + ii) * HW + jj] = acc[i][j] * inv_s + mterm;
        }
    }
}

// ---------------------------------------------------------------------------
// Kernel 3: row softmax in place on g_energy. One 256-thread block per row.
// Row kept register-resident (16 floats/thread).
// ---------------------------------------------------------------------------
__global__ void softmax_kernel() {
    const size_t row = blockIdx.x;     // n*HW + i
    float* E = g_energy + row * HW;
    const int tid = threadIdx.x;

    float v[16];
    float m = -1e30f;
    #pragma unroll
    for (int t = 0; t < 16; t++) {
        v[t] = E[t * 256 + tid];
        m = fmaxf(m, v[t]);
    }

    __shared__ float sred[8];
    #pragma unroll
    for (int o = 16; o > 0; o >>= 1)
        m = fmaxf(m, __shfl_xor_sync(0xffffffffu, m, o));
    if ((tid & 31) == 0) sred[tid >> 5] = m;
    __syncthreads();
    float mAll = sred[0];
    #pragma unroll
    for (int w = 1; w < 8; w++) mAll = fmaxf(mAll, sred[w]);

    float s = 0.0f;
    #pragma unroll
    for (int t = 0; t < 16; t++) {
        v[t] = __expf(v[t] - mAll);
        s += v[t];
    }
    #pragma unroll
    for (int o = 16; o > 0; o >>= 1)
        s += __shfl_xor_sync(0xffffffffu, s, o);
    __syncthreads();                       // everyone done reading max slots
    if ((tid & 31) == 0) sred[tid >> 5] = s;
    __syncthreads();
    float sAll = 0.0f;
    #pragma unroll
    for (int w = 0; w < 8; w++) sAll += sred[w];

    const float r = 1.0f / sAll;
    #pragma unroll
    for (int t = 0; t < 16; t++)
        E[t * 256 + tid] = v[t] * r;
}

// ---------------------------------------------------------------------------
// Kernel 4: out[n,c,i] = (sum_j weight[n,i,j] * feat[n,c,j]) * mask[n,i]
// F = g_feat[n]: [COUT, HW] (j contiguous); Wg = g_energy[n]: [HW, HW] (j contig)
// NT GEMM: M=COUT (c), N=HW (i), K=HW (j)
// ---------------------------------------------------------------------------
__global__ void out_kernel(const float* __restrict__ mask,
                           float* __restrict__ out) {
    __shared__ float As[16][64];   // As[k][m] = F[c0+m, k0+k]
    __shared__ float Bs[16][64];   // Bs[k][p] = Wg[i0+p, k0+k]

    const int n  = blockIdx.z;
    const int i0 = blockIdx.x * 64;
    const int c0 = blockIdx.y * 64;
    const int tx = threadIdx.x, ty = threadIdx.y;
    const int tid = ty * 16 + tx;
    const float* F  = g_feat   + (size_t)n * COUT * HW;
    const float* Wg = g_energy + (size_t)n * HW * HW;

    float acc[4][4] = {};

    for (int k0 = 0; k0 < HW; k0 += 16) {
        #pragma unroll
        for (int i = tid; i < 64 * 16; i += 256) {
            int m = i >> 4, k = i & 15;
            As[k][m] = F[(size_t)(c0 + m) * HW + k0 + k];
        }
        #pragma unroll
        for (int i = tid; i < 64 * 16; i += 256) {
            int p = i >> 4, k = i & 15;
            Bs[k][p] = Wg[(size_t)(i0 + p) * HW + k0 + k];
        }
        __syncthreads();
        #pragma unroll
        for (int k = 0; k < 16; k++) {
            float a[4], b[4];
            #pragma unroll
            for (int i = 0; i < 4; i++) a[i] = As[k][ty * 4 + i];
            #pragma unroll
            for (int j = 0; j < 4; j++) b[j] = Bs[k][tx * 4 + j];
            #pragma unroll
            for (int i = 0; i < 4; i++)
                #pragma unroll
                for (int j = 0; j < 4; j++)
                    acc[i][j] = fmaf(a[i], b[j], acc[i][j]);
        }
        __syncthreads();
    }

    #pragma unroll
    for (int i = 0; i < 4; i++) {
        int c = c0 + ty * 4 + i;
        #pragma unroll
        for (int j = 0; j < 4; j++) {
            int ii = i0 + tx * 4 + j;
            out[((size_t)n * COUT + c) * HW + ii] =
                acc[i][j] * mask[(size_t)n * HW + ii];
        }
    }
}

// ---------------------------------------------------------------------------
extern "C" void kernel_launch(void* const* d_in, const int* in_sizes, int n_in,
                              void* d_out, int out_size) {
    const float* x           = (const float*)d_in[0];
    const float* mask        = (const float*)d_in[1];
    const float* reduc_w     = (const float*)d_in[2];
    const float* reduc_gamma = (const float*)d_in[3];
    const float* reduc_beta  = (const float*)d_in[4];
    const float* reduc_mean  = (const float*)d_in[5];
    const float* reduc_var   = (const float*)d_in[6];
    const float* att_w       = (const float*)d_in[7];
    const float* att_gamma   = (const float*)d_in[8];
    const float* att_beta    = (const float*)d_in[9];
    const float* att_mean    = (const float*)d_in[10];
    const float* att_var     = (const float*)d_in[11];
    float* out = (float*)d_out;

    dim3 thr(16, 16);

    // feat conv: OC=256
    conv_bn_relu_kernel<<<dim3(HW / 64, COUT / 64, NB), thr>>>(
        x, reduc_w, reduc_gamma, reduc_beta, reduc_mean, reduc_var, COUT, 0);
    // atten conv: OC=128
    conv_bn_relu_kernel<<<dim3(HW / 64, CATT / 64, NB), thr>>>(
        x, att_w, att_gamma, att_beta, att_mean, att_var, CATT, 1);

    energy_kernel<<<dim3(HW / 64, HW / 64, NB), thr>>>(mask);

    softmax_kernel<<<NB * HW, 256>>>();

    out_kernel<<<dim3(HW / 64, COUT / 64, NB), thr>>>(mask, out);
}

// round 4
// speedup vs baseline: 4.2110x; 4.2110x over previous
#include <cuda_runtime.h>
#include <cstdint>

#define NB   8
#define CIN  256
#define HW   4096
#define CATT 128
#define COUT 256

// Scratch (device globals; no allocation allowed)
__device__ float g_feat[(size_t)NB * COUT * HW];              // [n][c][pos]
__device__ float g_attT[(size_t)NB * HW * CATT];              // [n][pos][c] (K-major)
__device__ float g_energy[(size_t)NB * HW * HW];              // [n][i][j]

// ===========================================================================
// Helpers — family-neutral PTX only (sm_80+): mma.sync tf32, cp.async, cvt
// ===========================================================================
__device__ __forceinline__ uint32_t smem_u32(const void* p) {
    uint32_t a;
    asm("{ .reg .u64 t; cvta.to.shared.u64 t, %1; cvt.u32.u64 %0, t; }" : "=r"(a) : "l"(p));
    return a;
}
__device__ __forceinline__ void mma_tf32(float c[4],
        uint32_t a0, uint32_t a1, uint32_t a2, uint32_t a3,
        uint32_t b0, uint32_t b1) {
    asm volatile("mma.sync.aligned.m16n8k8.row.col.f32.tf32.tf32.f32 "
                 "{%0,%1,%2,%3}, {%4,%5,%6,%7}, {%8,%9}, {%0,%1,%2,%3};"
                 : "+f"(c[0]), "+f"(c[1]), "+f"(c[2]), "+f"(c[3])
                 : "r"(a0), "r"(a1), "r"(a2), "r"(a3), "r"(b0), "r"(b1));
}
__device__ __forceinline__ uint32_t f2tf32(float x) {
    uint32_t r; asm("cvt.rna.tf32.f32 %0, %1;" : "=r"(r) : "f"(x)); return r;
}
#define CP16(dst, src) asm volatile("cp.async.ca.shared.global [%0], [%1], 16;" :: "r"(dst), "l"(src))
#define CP_COMMIT()    asm volatile("cp.async.commit_group;" ::: "memory")
#define CP_WAIT1()     asm volatile("cp.async.wait_group 1;" ::: "memory")
#define CP_WAIT0()     asm volatile("cp.async.wait_group 0;" ::: "memory")

// ===========================================================================
// Kernel 1: 1x1 conv + BN + ReLU (SIMT). att branch stores transposed.
// ===========================================================================
__global__ void conv_bn_relu_kernel(const float* __restrict__ x,
                                    const float* __restrict__ w,
                                    const float* __restrict__ gamma,
                                    const float* __restrict__ beta,
                                    const float* __restrict__ mean,
                                    const float* __restrict__ var,
                                    int OC, int dest) {
    __shared__ float As[16][64];
    __shared__ float Bs[16][64];

    const int n  = blockIdx.z;
    const int p0 = blockIdx.x * 64;
    const int o0 = blockIdx.y * 64;
    const int tx = threadIdx.x, ty = threadIdx.y;
    const int tid = ty * 16 + tx;
    const float* X = x + (size_t)n * CIN * HW;

    float acc[4][4] = {};

    for (int k0 = 0; k0 < CIN; k0 += 16) {
        #pragma unroll
        for (int i = tid; i < 64 * 16; i += 256) {
            int m = i >> 4, k = i & 15;
            As[k][m] = w[(size_t)(o0 + m) * CIN + k0 + k];
        }
        #pragma unroll
        for (int i = tid; i < 16 * 64; i += 256) {
            int k = i >> 6, p = i & 63;
            Bs[k][p] = X[(size_t)(k0 + k) * HW + p0 + p];
        }
        __syncthreads();
        #pragma unroll
        for (int k = 0; k < 16; k++) {
            float a[4], b[4];
            #pragma unroll
            for (int i = 0; i < 4; i++) a[i] = As[k][ty * 4 + i];
            #pragma unroll
            for (int j = 0; j < 4; j++) b[j] = Bs[k][tx * 4 + j];
            #pragma unroll
            for (int i = 0; i < 4; i++)
                #pragma unroll
                for (int j = 0; j < 4; j++)
                    acc[i][j] = fmaf(a[i], b[j], acc[i][j]);
        }
        __syncthreads();
    }

    #pragma unroll
    for (int i = 0; i < 4; i++) {
        int o = o0 + ty * 4 + i;
        float inv  = gamma[o] * rsqrtf(var[o] + 1e-5f);
        float bias = beta[o] - mean[o] * inv;
        #pragma unroll
        for (int j = 0; j < 4; j++) {
            int p = p0 + tx * 4 + j;
            float v = fmaxf(acc[i][j] * inv + bias, 0.0f);
            if (dest)
                g_attT[((size_t)n * HW + p) * CATT + o] = v;
            else
                g_feat[((size_t)n * OC + o) * HW + p] = v;
        }
    }
}

// ===========================================================================
// Kernel 2: energy via mma.sync tf32.
// energy[i,j] = inv_s * sum_c QT[i,c]*QT[j,c] + (mask[j]-1)*1e8
// CTA: 128(i=M) x 128(j=N), K=128. A=QT rows i (row-major), B=QT rows j (col op).
// 8 warps: 2(M)x4(N), warp tile 64x32.
// ===========================================================================
#define E_LD 132                    // smem row stride (floats), conflict-free
#define E_SMEM (2 * 128 * E_LD * 4) // 135168 B

__global__ __launch_bounds__(256, 1)
void energy_mma_kernel(const float* __restrict__ mask) {
    extern __shared__ float sm[];
    float* As = sm;                 // [i_local][k] tf32 bits
    float* Bs = sm + 128 * E_LD;    // [j_local][k]

    const int tid  = threadIdx.x;
    const int wid  = tid >> 5, lane = tid & 31;
    const int n  = blockIdx.z;
    const int i0 = blockIdx.y * 128;
    const int j0 = blockIdx.x * 128;
    const float* attn = g_attT + (size_t)n * HW * CATT;

    // Fill both tiles, converting to tf32 (rna) once.
    #pragma unroll 4
    for (int idx = tid; idx < 4096; idx += 256) {
        int row = idx >> 5, ch = idx & 31;
        float4 va = *(const float4*)(attn + (size_t)(i0 + row) * CATT + ch * 4);
        float4 vb = *(const float4*)(attn + (size_t)(j0 + row) * CATT + ch * 4);
        uint32_t* pa = (uint32_t*)&As[row * E_LD + ch * 4];
        uint32_t* pb = (uint32_t*)&Bs[row * E_LD + ch * 4];
        pa[0] = f2tf32(va.x); pa[1] = f2tf32(va.y); pa[2] = f2tf32(va.z); pa[3] = f2tf32(va.w);
        pb[0] = f2tf32(vb.x); pb[1] = f2tf32(vb.y); pb[2] = f2tf32(vb.z); pb[3] = f2tf32(vb.w);
    }
    __syncthreads();

    const int wm = wid & 1, wn = wid >> 1;
    const int r = lane >> 2, kq = lane & 3;
    float cc[4][4][4] = {};

    #pragma unroll 4
    for (int ks = 0; ks < 16; ks++) {
        const int k8 = ks * 8;
        uint32_t af[4][4], bf[4][2];
        #pragma unroll
        for (int mt = 0; mt < 4; mt++) {
            int mb = wm * 64 + mt * 16;
            af[mt][0] = __float_as_uint(As[(mb + r) * E_LD + k8 + kq]);
            af[mt][1] = __float_as_uint(As[(mb + r + 8) * E_LD + k8 + kq]);
            af[mt][2] = __float_as_uint(As[(mb + r) * E_LD + k8 + kq + 4]);
            af[mt][3] = __float_as_uint(As[(mb + r + 8) * E_LD + k8 + kq + 4]);
        }
        #pragma unroll
        for (int nt = 0; nt < 4; nt++) {
            int nb = wn * 32 + nt * 8;
            bf[nt][0] = __float_as_uint(Bs[(nb + r) * E_LD + k8 + kq]);
            bf[nt][1] = __float_as_uint(Bs[(nb + r) * E_LD + k8 + kq + 4]);
        }
        #pragma unroll
        for (int mt = 0; mt < 4; mt++)
            #pragma unroll
            for (int nt = 0; nt < 4; nt++)
                mma_tf32(cc[mt][nt], af[mt][0], af[mt][1], af[mt][2], af[mt][3],
                         bf[nt][0], bf[nt][1]);
    }
    __syncthreads();

    // Stage C into smem (reuse As region): S[i_local][j_local], stride E_LD.
    float* S = sm;
    #pragma unroll
    for (int mt = 0; mt < 4; mt++) {
        int ib = wm * 64 + mt * 16 + r;
        #pragma unroll
        for (int nt = 0; nt < 4; nt++) {
            int jb = wn * 32 + nt * 8 + kq * 2;
            S[ib * E_LD + jb]           = cc[mt][nt][0];
            S[ib * E_LD + jb + 1]       = cc[mt][nt][1];
            S[(ib + 8) * E_LD + jb]     = cc[mt][nt][2];
            S[(ib + 8) * E_LD + jb + 1] = cc[mt][nt][3];
        }
    }
    __syncthreads();

    // Coalesced store with scale + mask term.
    const float inv_s = 0.08838834764831845f;   // 1/(1e-8+sqrt(128))
    #pragma unroll 4
    for (int idx = tid; idx < 4096; idx += 256) {
        int row = idx >> 5, ch = idx & 31;
        int j = j0 + ch * 4;
        float4 v = *(const float4*)&S[row * E_LD + ch * 4];
        float4 mm = *(const float4*)&mask[(size_t)n * HW + j];
        v.x = v.x * inv_s + (mm.x - 1.0f) * 1e8f;
        v.y = v.y * inv_s + (mm.y - 1.0f) * 1e8f;
        v.z = v.z * inv_s + (mm.z - 1.0f) * 1e8f;
        v.w = v.w * inv_s + (mm.w - 1.0f) * 1e8f;
        *(float4*)&g_energy[((size_t)n * HW + i0 + row) * HW + j] = v;
    }
}

// ===========================================================================
// Kernel 3: row softmax (unchanged — at DRAM roof)
// ===========================================================================
__global__ void softmax_kernel() {
    const size_t row = blockIdx.x;
    float* E = g_energy + row * HW;
    const int tid = threadIdx.x;

    float v[16];
    float m = -1e30f;
    #pragma unroll
    for (int t = 0; t < 16; t++) {
        v[t] = E[t * 256 + tid];
        m = fmaxf(m, v[t]);
    }
    __shared__ float sred[8];
    #pragma unroll
    for (int o = 16; o > 0; o >>= 1)
        m = fmaxf(m, __shfl_xor_sync(0xffffffffu, m, o));
    if ((tid & 31) == 0) sred[tid >> 5] = m;
    __syncthreads();
    float mAll = sred[0];
    #pragma unroll
    for (int w = 1; w < 8; w++) mAll = fmaxf(mAll, sred[w]);

    float s = 0.0f;
    #pragma unroll
    for (int t = 0; t < 16; t++) { v[t] = __expf(v[t] - mAll); s += v[t]; }
    #pragma unroll
    for (int o = 16; o > 0; o >>= 1)
        s += __shfl_xor_sync(0xffffffffu, s, o);
    __syncthreads();
    if ((tid & 31) == 0) sred[tid >> 5] = s;
    __syncthreads();
    float sAll = 0.0f;
    #pragma unroll
    for (int w = 0; w < 8; w++) sAll += sred[w];

    const float r = 1.0f / sAll;
    #pragma unroll
    for (int t = 0; t < 16; t++) E[t * 256 + tid] = v[t] * r;
}

// ===========================================================================
// Kernel 4: out via mma.sync tf32 + cp.async 3-stage pipeline.
// D[i,c] = sum_j Wg[i,j]*F[c,j]; out[n,c,i] = D[i,c]*mask[i]
// CTA: M=128(i) x N=128(c), K=4096, Kt=32. 8 warps 2(M)x4(N), warp 64x32.
// ===========================================================================
#define O_LD 36                       // smem k-row stride (floats)
#define O_STAGE (2 * 128 * O_LD * 4)  // 36864 B per stage (A+B)
#define O_SMEM  (3 * O_STAGE)         // 110592 B
#define O_NIT   128                   // 4096/32

__global__ __launch_bounds__(256, 1)
void out_mma_kernel(const float* __restrict__ mask, float* __restrict__ out) {
    extern __shared__ char smc[];
    const uint32_t sb = smem_u32(smc);
    const int tid  = threadIdx.x;
    const int wid  = tid >> 5, lane = tid & 31;
    const int n  = blockIdx.z;
    const int i0 = blockIdx.x * 128;
    const int c0 = blockIdx.y * 128;
    const float* Wg = g_energy + (size_t)n * HW * HW;     // [i][j]
    const float* F  = g_feat   + (size_t)n * COUT * HW;   // [c][j]

    // Stage layout: A at s*O_STAGE (128 rows x 144B), B at +18432.
    auto load_stage = [&](int s, int kt) {
        uint32_t base = sb + (uint32_t)s * O_STAGE;
        #pragma unroll
        for (int idx = tid; idx < 1024; idx += 256) {
            int row = idx >> 3, ch = idx & 7;
            CP16(base + row * 144 + ch * 16,
                 Wg + (size_t)(i0 + row) * HW + kt + ch * 4);
            CP16(base + 18432 + row * 144 + ch * 16,
                 F + (size_t)(c0 + row) * HW + kt + ch * 4);
        }
        CP_COMMIT();
    };

    load_stage(0, 0);
    load_stage(1, 32);

    const int wm = wid & 1, wn = wid >> 1;
    const int r = lane >> 2, kq = lane & 3;
    float cc[4][4][4] = {};

    for (int it = 0; it < O_NIT; ++it) {
        CP_WAIT1();
        __syncthreads();
        const float* As = (const float*)(smc + (it % 3) * O_STAGE);
        const float* Bs = As + 128 * O_LD;
        #pragma unroll
        for (int ks = 0; ks < 4; ks++) {
            const int k8 = ks * 8;
            uint32_t af[4][4], bf[4][2];
            #pragma unroll
            for (int mt = 0; mt < 4; mt++) {
                int mb = wm * 64 + mt * 16;
                af[mt][0] = __float_as_uint(As[(mb + r) * O_LD + k8 + kq]);
                af[mt][1] = __float_as_uint(As[(mb + r + 8) * O_LD + k8 + kq]);
                af[mt][2] = __float_as_uint(As[(mb + r) * O_LD + k8 + kq + 4]);
                af[mt][3] = __float_as_uint(As[(mb + r + 8) * O_LD + k8 + kq + 4]);
            }
            #pragma unroll
            for (int nt = 0; nt < 4; nt++) {
                int nb = wn * 32 + nt * 8;
                bf[nt][0] = __float_as_uint(Bs[(nb + r) * O_LD + k8 + kq]);
                bf[nt][1] = __float_as_uint(Bs[(nb + r) * O_LD + k8 + kq + 4]);
            }
            #pragma unroll
            for (int mt = 0; mt < 4; mt++)
                #pragma unroll
                for (int nt = 0; nt < 4; nt++)
                    mma_tf32(cc[mt][nt], af[mt][0], af[mt][1], af[mt][2], af[mt][3],
                             bf[nt][0], bf[nt][1]);
        }
        __syncthreads();
        if (it + 2 < O_NIT) load_stage((it + 2) % 3, (it + 2) * 32);
        else CP_COMMIT();     // empty group keeps wait_group bookkeeping exact
    }
    CP_WAIT0();
    __syncthreads();

    // Stage C into smem: S[c_local][i_local], stride 132.
    float* S = (float*)smc;
    #pragma unroll
    for (int mt = 0; mt < 4; mt++) {
        int ib = wm * 64 + mt * 16 + r;
        #pragma unroll
        for (int nt = 0; nt < 4; nt++) {
            int cb = wn * 32 + nt * 8 + kq * 2;
            S[cb * 132 + ib]           = cc[mt][nt][0];
            S[(cb + 1) * 132 + ib]     = cc[mt][nt][1];
            S[cb * 132 + ib + 8]       = cc[mt][nt][2];
            S[(cb + 1) * 132 + ib + 8] = cc[mt][nt][3];
        }
    }
    __syncthreads();

    // Coalesced store over i with mask.
    #pragma unroll 4
    for (int idx = tid; idx < 4096; idx += 256) {
        int row = idx >> 5, ch = idx & 31;
        int ii = i0 + ch * 4;
        float4 v = *(const float4*)&S[row * 132 + ch * 4];
        float4 mm = *(const float4*)&mask[(size_t)n * HW + ii];
        v.x *= mm.x; v.y *= mm.y; v.z *= mm.z; v.w *= mm.w;
        *(float4*)&out[((size_t)n * COUT + c0 + row) * HW + ii] = v;
    }
}

// ===========================================================================
extern "C" void kernel_launch(void* const* d_in, const int* in_sizes, int n_in,
                              void* d_out, int out_size) {
    const float* x           = (const float*)d_in[0];
    const float* mask        = (const float*)d_in[1];
    const float* reduc_w     = (const float*)d_in[2];
    const float* reduc_gamma = (const float*)d_in[3];
    const float* reduc_beta  = (const float*)d_in[4];
    const float* reduc_mean  = (const float*)d_in[5];
    const float* reduc_var   = (const float*)d_in[6];
    const float* att_w       = (const float*)d_in[7];
    const float* att_gamma   = (const float*)d_in[8];
    const float* att_beta    = (const float*)d_in[9];
    const float* att_mean    = (const float*)d_in[10];
    const float* att_var     = (const float*)d_in[11];
    float* out = (float*)d_out;

    static bool attr_done = false;
    if (!attr_done) {
        cudaFuncSetAttribute(energy_mma_kernel, cudaFuncAttributeMaxDynamicSharedMemorySize, E_SMEM);
        cudaFuncSetAttribute(out_mma_kernel,    cudaFuncAttributeMaxDynamicSharedMemorySize, O_SMEM);
        attr_done = true;
    }

    dim3 thr(16, 16);
    conv_bn_relu_kernel<<<dim3(HW / 64, COUT / 64, NB), thr>>>(
        x, reduc_w, reduc_gamma, reduc_beta, reduc_mean, reduc_var, COUT, 0);
    conv_bn_relu_kernel<<<dim3(HW / 64, CATT / 64, NB), thr>>>(
        x, att_w, att_gamma, att_beta, att_mean, att_var, CATT, 1);

    energy_mma_kernel<<<dim3(HW / 128, HW / 128, NB), 256, E_SMEM>>>(mask);

    softmax_kernel<<<NB * HW, 256>>>();

    out_mma_kernel<<<dim3(HW / 128, COUT / 128, NB), 256, O_SMEM>>>(mask, out);
}

// round 6
// speedup vs baseline: 4.9209x; 1.1686x over previous
#include <cuda_runtime.h>
#include <cstdint>

#define NB   8
#define CIN  256
#define HW   4096
#define CATT 128
#define COUT 256

// Scratch (device globals; no allocation allowed)
__device__ float g_feat[(size_t)NB * COUT * HW];              // [n][c][pos]
__device__ float g_attT[(size_t)NB * HW * CATT];              // [n][pos][c] (K-major)
__device__ float g_energy[(size_t)NB * HW * HW];              // [n][i][j]

// ===========================================================================
// Helpers — family-neutral PTX only (sm_80+)
// ===========================================================================
__device__ __forceinline__ uint32_t smem_u32(const void* p) {
    uint32_t a;
    asm("{ .reg .u64 t; cvta.to.shared.u64 t, %1; cvt.u32.u64 %0, t; }" : "=r"(a) : "l"(p));
    return a;
}
__device__ __forceinline__ void mma_tf32(float c[4],
        uint32_t a0, uint32_t a1, uint32_t a2, uint32_t a3,
        uint32_t b0, uint32_t b1) {
    asm volatile("mma.sync.aligned.m16n8k8.row.col.f32.tf32.tf32.f32 "
                 "{%0,%1,%2,%3}, {%4,%5,%6,%7}, {%8,%9}, {%0,%1,%2,%3};"
                 : "+f"(c[0]), "+f"(c[1]), "+f"(c[2]), "+f"(c[3])
                 : "r"(a0), "r"(a1), "r"(a2), "r"(a3), "r"(b0), "r"(b1));
}
__device__ __forceinline__ uint32_t f2tf32(float x) {
    uint32_t r; asm("cvt.rna.tf32.f32 %0, %1;" : "=r"(r) : "f"(x)); return r;
}
#define CP16(dst, src) asm volatile("cp.async.ca.shared.global [%0], [%1], 16;" :: "r"(dst), "l"(src))
#define CP_COMMIT()    asm volatile("cp.async.commit_group;" ::: "memory")
#define CP_WAIT1()     asm volatile("cp.async.wait_group 1;" ::: "memory")
#define CP_WAIT0()     asm volatile("cp.async.wait_group 0;" ::: "memory")

// ===========================================================================
// Kernel 1: 1x1 conv + BN + ReLU.  Tile: 64(o) x 128(p), 256 thr, micro 4x8,
// 2-stage cp.async (K-step 16).  att branch stores transposed [pos][c].
// ===========================================================================
__global__ __launch_bounds__(256)
void conv_bn_relu_kernel(const float* __restrict__ x,
                         const float* __restrict__ w,
                         const float* __restrict__ gamma,
                         const float* __restrict__ beta,
                         const float* __restrict__ mean,
                         const float* __restrict__ var,
                         int OC, int dest) {
    __shared__ float Ws[2][64][20];    // [m][k] padded
    __shared__ float Xs[2][16][132];   // [k][p] padded

    const int n  = blockIdx.z;
    const int p0 = blockIdx.x * 128;
    const int o0 = blockIdx.y * 64;
    const int tid = threadIdx.x;
    const int tx = tid & 15, ty = tid >> 4;
    const float* X = x + (size_t)n * CIN * HW;

    auto load_stage = [&](int s, int k0) {
        // W: 64 m-rows x 16 k (4 CP16/row)
        {
            int m = tid >> 2, k4 = tid & 3;            // tid < 256 exactly
            CP16(smem_u32(&Ws[s][m][k4 * 4]), w + (size_t)(o0 + m) * CIN + k0 + k4 * 4);
        }
        // X: 16 k-rows x 128 p (32 CP16/row) = 512
        #pragma unroll
        for (int i = tid; i < 512; i += 256) {
            int k = i >> 5, p4 = i & 31;
            CP16(smem_u32(&Xs[s][k][p4 * 4]), X + (size_t)(k0 + k) * HW + p0 + p4 * 4);
        }
        CP_COMMIT();
    };

    float acc[4][8] = {};
    load_stage(0, 0);
    load_stage(1, 16);

    for (int ks = 0; ks < 16; ks++) {
        CP_WAIT1();
        __syncthreads();
        const int s = ks & 1;
        #pragma unroll
        for (int k = 0; k < 16; k++) {
            float a[4];
            #pragma unroll
            for (int i = 0; i < 4; i++) a[i] = Ws[s][ty * 4 + i][k];
            float4 b0 = *(const float4*)&Xs[s][k][tx * 8];
            float4 b1 = *(const float4*)&Xs[s][k][tx * 8 + 4];
            float b[8] = {b0.x, b0.y, b0.z, b0.w, b1.x, b1.y, b1.z, b1.w};
            #pragma unroll
            for (int i = 0; i < 4; i++)
                #pragma unroll
                for (int j = 0; j < 8; j++)
                    acc[i][j] = fmaf(a[i], b[j], acc[i][j]);
        }
        __syncthreads();
        if (ks + 2 < 16) load_stage(s, (ks + 2) * 16);
        else CP_COMMIT();
    }
    CP_WAIT0();

    // BN + ReLU + store
    float v[4][8];
    #pragma unroll
    for (int i = 0; i < 4; i++) {
        int o = o0 + ty * 4 + i;
        float inv  = gamma[o] * rsqrtf(var[o] + 1e-5f);
        float bias = beta[o] - mean[o] * inv;
        #pragma unroll
        for (int j = 0; j < 8; j++)
            v[i][j] = fmaxf(acc[i][j] * inv + bias, 0.0f);
    }
    if (dest) {
        // g_attT[n][p][c]: per p, 4 consecutive c -> float4
        #pragma unroll
        for (int j = 0; j < 8; j++) {
            int p = p0 + tx * 8 + j;
            float4 q = make_float4(v[0][j], v[1][j], v[2][j], v[3][j]);
            *(float4*)&g_attT[((size_t)n * HW + p) * CATT + o0 + ty * 4] = q;
        }
    } else {
        #pragma unroll
        for (int i = 0; i < 4; i++) {
            int o = o0 + ty * 4 + i;
            float4 q0 = make_float4(v[i][0], v[i][1], v[i][2], v[i][3]);
            float4 q1 = make_float4(v[i][4], v[i][5], v[i][6], v[i][7]);
            float* dst = &g_feat[((size_t)n * OC + o) * HW + p0 + tx * 8];
            *(float4*)dst = q0;
            *(float4*)(dst + 4) = q1;
        }
    }
}

// ===========================================================================
// Kernel 2: energy via mma.sync tf32.
// energy[i,j] = inv_s * sum_c QT[i,c]*QT[j,c] + (mask[j]-1)*1e8
// CTA: 128(i=M) x 256(j=N), K=128. 8 warps 2(M)x4(N), warp tile 64x64.
// ===========================================================================
#define E_LD 132
#define E_SLD 260
#define E_SMEM ((128 + 256) * E_LD * 4)   // 202752 B

__global__ __launch_bounds__(256, 1)
void energy_mma_kernel(const float* __restrict__ mask) {
    extern __shared__ float sm[];
    float* As = sm;                 // 128 rows x E_LD (i)
    float* Bs = sm + 128 * E_LD;    // 256 rows x E_LD (j)

    const int tid  = threadIdx.x;
    const int wid  = tid >> 5, lane = tid & 31;
    const int n  = blockIdx.z;
    const int i0 = blockIdx.y * 128;
    const int j0 = blockIdx.x * 256;
    const float* attn = g_attT + (size_t)n * HW * CATT;

    // Fill tiles, tf32(rna) conversion at fill.
    #pragma unroll 4
    for (int idx = tid; idx < 4096; idx += 256) {
        int row = idx >> 5, ch = idx & 31;
        float4 va = *(const float4*)(attn + (size_t)(i0 + row) * CATT + ch * 4);
        uint4 t = make_uint4(f2tf32(va.x), f2tf32(va.y), f2tf32(va.z), f2tf32(va.w));
        *(uint4*)&As[row * E_LD + ch * 4] = t;
    }
    #pragma unroll 4
    for (int idx = tid; idx < 8192; idx += 256) {
        int row = idx >> 5, ch = idx & 31;
        float4 vb = *(const float4*)(attn + (size_t)(j0 + row) * CATT + ch * 4);
        uint4 t = make_uint4(f2tf32(vb.x), f2tf32(vb.y), f2tf32(vb.z), f2tf32(vb.w));
        *(uint4*)&Bs[row * E_LD + ch * 4] = t;
    }
    __syncthreads();

    const int wm = wid & 1, wn = wid >> 1;     // wn 0..3
    const int r = lane >> 2, kq = lane & 3;
    float cc[4][8][4] = {};

    #pragma unroll 2
    for (int ks = 0; ks < 16; ks++) {
        const int k8 = ks * 8;
        uint32_t af[4][4];
        #pragma unroll
        for (int mt = 0; mt < 4; mt++) {
            int mb = wm * 64 + mt * 16;
            af[mt][0] = __float_as_uint(As[(mb + r) * E_LD + k8 + kq]);
            af[mt][1] = __float_as_uint(As[(mb + r + 8) * E_LD + k8 + kq]);
            af[mt][2] = __float_as_uint(As[(mb + r) * E_LD + k8 + kq + 4]);
            af[mt][3] = __float_as_uint(As[(mb + r + 8) * E_LD + k8 + kq + 4]);
        }
        #pragma unroll
        for (int nt = 0; nt < 8; nt++) {
            int nb = wn * 64 + nt * 8;
            uint32_t b0 = __float_as_uint(Bs[(nb + r) * E_LD + k8 + kq]);
            uint32_t b1 = __float_as_uint(Bs[(nb + r) * E_LD + k8 + kq + 4]);
            #pragma unroll
            for (int mt = 0; mt < 4; mt++)
                mma_tf32(cc[mt][nt], af[mt][0], af[mt][1], af[mt][2], af[mt][3], b0, b1);
        }
    }
    __syncthreads();

    // Stage C: S[i_local][j_local], stride E_SLD.
    float* S = sm;
    #pragma unroll
    for (int mt = 0; mt < 4; mt++) {
        int ib = wm * 64 + mt * 16 + r;
        #pragma unroll
        for (int nt = 0; nt < 8; nt++) {
            int jb = wn * 64 + nt * 8 + kq * 2;
            S[ib * E_SLD + jb]           = cc[mt][nt][0];
            S[ib * E_SLD + jb + 1]       = cc[mt][nt][1];
            S[(ib + 8) * E_SLD + jb]     = cc[mt][nt][2];
            S[(ib + 8) * E_SLD + jb + 1] = cc[mt][nt][3];
        }
    }
    __syncthreads();

    const float inv_s = 0.08838834764831845f;   // 1/(1e-8+sqrt(128))
    #pragma unroll 4
    for (int idx = tid; idx < 8192; idx += 256) {
        int row = idx >> 6, ch = idx & 63;
        int j = j0 + ch * 4;
        float4 v = *(const float4*)&S[row * E_SLD + ch * 4];
        float4 mm = *(const float4*)&mask[(size_t)n * HW + j];
        v.x = v.x * inv_s + (mm.x - 1.0f) * 1e8f;
        v.y = v.y * inv_s + (mm.y - 1.0f) * 1e8f;
        v.z = v.z * inv_s + (mm.z - 1.0f) * 1e8f;
        v.w = v.w * inv_s + (mm.w - 1.0f) * 1e8f;
        *(float4*)&g_energy[((size_t)n * HW + i0 + row) * HW + j] = v;
    }
}

// ===========================================================================
// Kernel 3: row softmax (unchanged — at DRAM roof)
// ===========================================================================
__global__ void softmax_kernel() {
    const size_t row = blockIdx.x;
    float* E = g_energy + row * HW;
    const int tid = threadIdx.x;

    float v[16];
    float m = -1e30f;
    #pragma unroll
    for (int t = 0; t < 16; t++) {
        v[t] = E[t * 256 + tid];
        m = fmaxf(m, v[t]);
    }
    __shared__ float sred[8];
    #pragma unroll
    for (int o = 16; o > 0; o >>= 1)
        m = fmaxf(m, __shfl_xor_sync(0xffffffffu, m, o));
    if ((tid & 31) == 0) sred[tid >> 5] = m;
    __syncthreads();
    float mAll = sred[0];
    #pragma unroll
    for (int w = 1; w < 8; w++) mAll = fmaxf(mAll, sred[w]);

    float s = 0.0f;
    #pragma unroll
    for (int t = 0; t < 16; t++) { v[t] = __expf(v[t] - mAll); s += v[t]; }
    #pragma unroll
    for (int o = 16; o > 0; o >>= 1)
        s += __shfl_xor_sync(0xffffffffu, s, o);
    __syncthreads();
    if ((tid & 31) == 0) sred[tid >> 5] = s;
    __syncthreads();
    float sAll = 0.0f;
    #pragma unroll
    for (int w = 0; w < 8; w++) sAll += sred[w];

    const float r = 1.0f / sAll;
    #pragma unroll
    for (int t = 0; t < 16; t++) E[t * 256 + tid] = v[t] * r;
}

// ===========================================================================
// Kernel 4: out via mma.sync tf32 + cp.async 3-stage.
// D[i,c] = sum_j Wg[i,j]*F[c,j]; out[n,c,i] = D[i,c]*mask[i]
// CTA: M=128(i) x N=256(c, full COUT -> energy read once), K=4096, Kt=32.
// 8 warps 2(M)x4(N), warp tile 64x64.
// ===========================================================================
#define O_LD 36
#define O_STAGE ((128 + 256) * O_LD * 4)  // 55296 B
#define O_SMEM  (3 * O_STAGE)             // 165888 B
#define O_NIT   128                       // 4096/32

__global__ __launch_bounds__(256, 1)
void out_mma_kernel(const float* __restrict__ mask, float* __restrict__ out) {
    extern __shared__ char smc[];
    const uint32_t sb = smem_u32(smc);
    const int tid  = threadIdx.x;
    const int wid  = tid >> 5, lane = tid & 31;
    const int n  = blockIdx.y;
    const int i0 = blockIdx.x * 128;
    const float* Wg = g_energy + (size_t)n * HW * HW;     // [i][j]
    const float* F  = g_feat   + (size_t)n * COUT * HW;   // [c][j]

    auto load_stage = [&](int s, int kt) {
        uint32_t base = sb + (uint32_t)s * O_STAGE;
        #pragma unroll
        for (int idx = tid; idx < 3072; idx += 256) {
            if (idx < 1024) {
                int row = idx >> 3, ch = idx & 7;
                CP16(base + row * 144 + ch * 16,
                     Wg + (size_t)(i0 + row) * HW + kt + ch * 4);
            } else {
                int q = idx - 1024;
                int row = q >> 3, ch = q & 7;
                CP16(base + 18432 + row * 144 + ch * 16,
                     F + (size_t)row * HW + kt + ch * 4);
            }
        }
        CP_COMMIT();
    };

    load_stage(0, 0);
    load_stage(1, 32);

    const int wm = wid & 1, wn = wid >> 1;
    const int r = lane >> 2, kq = lane & 3;
    float cc[4][8][4] = {};

    for (int it = 0; it < O_NIT; ++it) {
        CP_WAIT1();
        __syncthreads();
        const float* As = (const float*)(smc + (it % 3) * O_STAGE);
        const float* Bs = As + 128 * O_LD;
        #pragma unroll
        for (int ks = 0; ks < 4; ks++) {
            const int k8 = ks * 8;
            uint32_t af[4][4];
            #pragma unroll
            for (int mt = 0; mt < 4; mt++) {
                int mb = wm * 64 + mt * 16;
                af[mt][0] = __float_as_uint(As[(mb + r) * O_LD + k8 + kq]);
                af[mt][1] = __float_as_uint(As[(mb + r + 8) * O_LD + k8 + kq]);
                af[mt][2] = __float_as_uint(As[(mb + r) * O_LD + k8 + kq + 4]);
                af[mt][3] = __float_as_uint(As[(mb + r + 8) * O_LD + k8 + kq + 4]);
            }
            #pragma unroll
            for (int nt = 0; nt < 8; nt++) {
                int nb = wn * 64 + nt * 8;
                uint32_t b0 = __float_as_uint(Bs[(nb + r) * O_LD + k8 + kq]);
                uint32_t b1 = __float_as_uint(Bs[(nb + r) * O_LD + k8 + kq + 4]);
                #pragma unroll
                for (int mt = 0; mt < 4; mt++)
                    mma_tf32(cc[mt][nt], af[mt][0], af[mt][1], af[mt][2], af[mt][3], b0, b1);
            }
        }
        __syncthreads();
        if (it + 2 < O_NIT) load_stage((it + 2) % 3, (it + 2) * 32);
        else CP_COMMIT();
    }
    CP_WAIT0();
    __syncthreads();

    // Stage C: S[c_local][i_local], stride 132.
    float* S = (float*)smc;
    #pragma unroll
    for (int mt = 0; mt < 4; mt++) {
        int ib = wm * 64 + mt * 16 + r;
        #pragma unroll
        for (int nt = 0; nt < 8; nt++) {
            int cb = wn * 64 + nt * 8 + kq * 2;
            S[cb * 132 + ib]           = cc[mt][nt][0];
            S[(cb + 1) * 132 + ib]     = cc[mt][nt][1];
            S[cb * 132 + ib + 8]       = cc[mt][nt][2];
            S[(cb + 1) * 132 + ib + 8] = cc[mt][nt][3];
        }
    }
    __syncthreads();

    // Coalesced store over i with mask. 256 c-rows x 32 float4.
    #pragma unroll 4
    for (int idx = tid; idx < 8192; idx += 256) {
        int row = idx >> 5, ch = idx & 31;
        int ii = i0 + ch * 4;
        float4 v = *(const float4*)&S[row * 132 + ch * 4];
        float4 mm = *(const float4*)&mask[(size_t)n * HW + ii];
        v.x *= mm.x; v.y *= mm.y; v.z *= mm.z; v.w *= mm.w;
        *(float4*)&out[((size_t)n * COUT + row) * HW + ii] = v;
    }
}

// ===========================================================================
extern "C" void kernel_launch(void* const* d_in, const int* in_sizes, int n_in,
                              void* d_out, int out_size) {
    const float* x           = (const float*)d_in[0];
    const float* mask        = (const float*)d_in[1];
    const float* reduc_w     = (const float*)d_in[2];
    const float* reduc_gamma = (const float*)d_in[3];
    const float* reduc_beta  = (const float*)d_in[4];
    const float* reduc_mean  = (const float*)d_in[5];
    const float* reduc_var   = (const float*)d_in[6];
    const float* att_w       = (const float*)d_in[7];
    const float* att_gamma   = (const float*)d_in[8];
    const float* att_beta    = (const float*)d_in[9];
    const float* att_mean    = (const float*)d_in[10];
    const float* att_var     = (const float*)d_in[11];
    float* out = (float*)d_out;

    cudaFuncSetAttribute(energy_mma_kernel, cudaFuncAttributeMaxDynamicSharedMemorySize, E_SMEM);
    cudaFuncSetAttribute(out_mma_kernel,    cudaFuncAttributeMaxDynamicSharedMemorySize, O_SMEM);

    conv_bn_relu_kernel<<<dim3(HW / 128, COUT / 64, NB), 256>>>(
        x, reduc_w, reduc_gamma, reduc_beta, reduc_mean, reduc_var, COUT, 0);
    conv_bn_relu_kernel<<<dim3(HW / 128, CATT / 64, NB), 256>>>(
        x, att_w, att_gamma, att_beta, att_mean, att_var, CATT, 1);

    energy_mma_kernel<<<dim3(HW / 256, HW / 128, NB), 256, E_SMEM>>>(mask);

    softmax_kernel<<<NB * HW, 256>>>();

    out_mma_kernel<<<dim3(HW / 128, NB), 256, O_SMEM>>>(mask, out);
}